// round 5
// baseline (speedup 1.0000x reference)
#include <cuda_runtime.h>

namespace {

constexpr int NC  = 64;    // coarse samples
constexpr int NA  = 128;   // total samples in fine pass
constexpr int HID = 128;
constexpr int WPB = 4;     // warps (rays) per block

using u64 = unsigned long long;

__device__ __forceinline__ u64 f32x2_fma(u64 a, u64 b, u64 c) {
    u64 d;
    asm("fma.rn.f32x2 %0, %1, %2, %3;" : "=l"(d) : "l"(a), "l"(b), "l"(c));
    return d;
}
__device__ __forceinline__ u64 pack2(float lo, float hi) {
    u64 d;
    asm("mov.b64 %0, {%1, %2};" : "=l"(d) : "f"(lo), "f"(hi));
    return d;
}
__device__ __forceinline__ float2 unpack2(u64 v) {
    float2 r;
    asm("mov.b64 {%0, %1}, %2;" : "=f"(r.x), "=f"(r.y) : "l"(v));
    return r;
}

struct alignas(16) WarpSh {
    float4 ab2[HID / 2];        // {a_j, b_j, a_j+1, b_j+1} : 1024 B
    union {                     // lifetimes disjoint:
        float cdf[68];          //   cdf[0..64]  (pdf->sampling)
        struct {
            float  zs[NA];      //   sorted z            : 512 B
            float4 outs[NA];    //   sorted (r,g,b,sig)   : 2048 B
        } m;                    //   (merge->fine composite)
    } u;
    float kc[NC];               // coarse keys (sorted by construction)
    float kf[NC];               // fine keys
};                              // 4096 B

// MLP for 2 samples (layer1 collapsed to per-ray affine in z).
// One abd LDS.128 feeds two hidden units. Channel-major packed accumulators.
__device__ __forceinline__ void mlp2(
    const float4* __restrict__ ab2,       // per-warp {a0,b0,a1,b1}
    const float4* __restrict__ W2s,       // (wx, wy, wz, ww)
    u64 bxy, u64 bzw,
    float z0, float z1, float4& o0, float4& o1)
{
    const u64 zz = pack2(z0, z1);
    u64 a0xy = bxy, a0zw = bzw, a1xy = bxy, a1zw = bzw;

#pragma unroll 4
    for (int j2 = 0; j2 < HID / 2; j2++) {
        float4 p  = ab2[j2];             // broadcast LDS.128 (two hidden units)
        float4 wA = W2s[2 * j2];         // broadcast LDS.128
        float4 wB = W2s[2 * j2 + 1];     // broadcast LDS.128
        // unit A
        {
            u64 aa = pack2(p.x, p.x);
            u64 bb = pack2(p.y, p.y);
            u64 h2 = f32x2_fma(zz, bb, aa);
            float2 t = unpack2(h2);
            float h0 = fmaxf(t.x, 0.0f);
            float h1 = fmaxf(t.y, 0.0f);
            u64 h00 = pack2(h0, h0);
            u64 h11 = pack2(h1, h1);
            u64 wxy = pack2(wA.x, wA.y);
            u64 wzw = pack2(wA.z, wA.w);
            a0xy = f32x2_fma(h00, wxy, a0xy);
            a0zw = f32x2_fma(h00, wzw, a0zw);
            a1xy = f32x2_fma(h11, wxy, a1xy);
            a1zw = f32x2_fma(h11, wzw, a1zw);
        }
        // unit B
        {
            u64 aa = pack2(p.z, p.z);
            u64 bb = pack2(p.w, p.w);
            u64 h2 = f32x2_fma(zz, bb, aa);
            float2 t = unpack2(h2);
            float h0 = fmaxf(t.x, 0.0f);
            float h1 = fmaxf(t.y, 0.0f);
            u64 h00 = pack2(h0, h0);
            u64 h11 = pack2(h1, h1);
            u64 wxy = pack2(wB.x, wB.y);
            u64 wzw = pack2(wB.z, wB.w);
            a0xy = f32x2_fma(h00, wxy, a0xy);
            a0zw = f32x2_fma(h00, wzw, a0zw);
            a1xy = f32x2_fma(h11, wxy, a1xy);
            a1zw = f32x2_fma(h11, wzw, a1zw);
        }
    }
    float2 v;
    v = unpack2(a0xy); o0.x = v.x; o0.y = v.y;
    v = unpack2(a0zw); o0.z = v.x; o0.w = v.y;
    v = unpack2(a1xy); o1.x = v.x; o1.y = v.y;
    v = unpack2(a1zw); o1.z = v.x; o1.w = v.y;
}

// Alpha compositing over K depth-sorted samples/lane (lane-major order).
// o[i] = (r, g, b, sigma). Returns warp-summed (r, g, b, depth) on all lanes.
template <int K>
__device__ __forceinline__ float4 composite(
    const float4* o, const float* z, const float* delta, float* w_out, int lane)
{
    float alpha[K], f[K];
    float prod = 1.0f;
#pragma unroll
    for (int i = 0; i < K; i++) {
        float sig = fmaxf(o[i].w, 0.0f);
        alpha[i] = 1.0f - __expf(-delta[i] * sig);
        f[i] = 1.0f - alpha[i] + 1e-10f;
        prod *= f[i];
    }

    // exclusive warp prefix-product of per-lane transmittance factors
    float sc = prod;
#pragma unroll
    for (int off = 1; off < 32; off <<= 1) {
        float v = __shfl_up_sync(0xffffffffu, sc, off);
        if (lane >= off) sc *= v;
    }
    float T = __shfl_up_sync(0xffffffffu, sc, 1);
    if (lane == 0) T = 1.0f;

    float rx = 0.f, ry = 0.f, rz = 0.f, dd = 0.f;
#pragma unroll
    for (int i = 0; i < K; i++) {
        float w = alpha[i] * T;
        if (w_out) w_out[i] = w;
        rx = fmaf(w, o[i].x, rx);
        ry = fmaf(w, o[i].y, ry);
        rz = fmaf(w, o[i].z, rz);
        dd = fmaf(w, z[i],   dd);
        T *= f[i];
    }
#pragma unroll
    for (int off = 16; off > 0; off >>= 1) {
        rx += __shfl_xor_sync(0xffffffffu, rx, off);
        ry += __shfl_xor_sync(0xffffffffu, ry, off);
        rz += __shfl_xor_sync(0xffffffffu, rz, off);
        dd += __shfl_xor_sync(0xffffffffu, dd, off);
    }
    return make_float4(rx, ry, rz, dd);
}

} // namespace

__global__ void __launch_bounds__(WPB * 32, 9)
nerf_kernel(const float* __restrict__ rays,
            const float* __restrict__ u_coarse,
            const float* __restrict__ u_fine,
            const float* __restrict__ u_jitter,
            const float* __restrict__ W1,   // (3, 128)
            const float* __restrict__ b1,   // (128,)
            const float* __restrict__ W2,   // (128, 4)
            const float* __restrict__ b2,   // (4,)
            float* __restrict__ out)        // (R, 8)
{
    __shared__ float4 W2s[HID];
    __shared__ float4 b2s;
    __shared__ WarpSh wsall[WPB];

    const int tid  = threadIdx.x;
    const int wid  = tid >> 5;
    const int lane = tid & 31;
    const int ray  = blockIdx.x * WPB + wid;

    W2s[tid] = reinterpret_cast<const float4*>(W2)[tid];   // blockDim == 128
    if (tid == 0) b2s = *reinterpret_cast<const float4*>(b2);
    __syncthreads();

    WarpSh& ws = wsall[wid];
    const float* rp = rays + ray * 8;   // broadcast loads
    const float ox = rp[0], oy = rp[1], oz = rp[2];
    const float dx = rp[3], dy = rp[4], dz = rp[5];
    const float nearv = rp[6], farv = rp[7];
    const float zscale = (farv - nearv) * (1.0f / NC);   // z = near + key*zscale

    // Per-ray layer-1 affine: lane handles units 4*lane .. 4*lane+3 (float4 rows)
    {
        float4 w0 = reinterpret_cast<const float4*>(W1)[lane];             // row 0
        float4 w1 = reinterpret_cast<const float4*>(W1 + HID)[lane];       // row 1
        float4 w2 = reinterpret_cast<const float4*>(W1 + 2 * HID)[lane];   // row 2
        float4 bb = reinterpret_cast<const float4*>(b1)[lane];
        float a0 = fmaf(ox, w0.x, fmaf(oy, w1.x, fmaf(oz, w2.x, bb.x)));
        float a1 = fmaf(ox, w0.y, fmaf(oy, w1.y, fmaf(oz, w2.y, bb.y)));
        float a2 = fmaf(ox, w0.z, fmaf(oy, w1.z, fmaf(oz, w2.z, bb.z)));
        float a3 = fmaf(ox, w0.w, fmaf(oy, w1.w, fmaf(oz, w2.w, bb.w)));
        float d0 = fmaf(dx, w0.x, fmaf(dy, w1.x, dz * w2.x));
        float d1 = fmaf(dx, w0.y, fmaf(dy, w1.y, dz * w2.y));
        float d2 = fmaf(dx, w0.z, fmaf(dy, w1.z, dz * w2.z));
        float d3 = fmaf(dx, w0.w, fmaf(dy, w1.w, dz * w2.w));
        ws.ab2[2 * lane]     = make_float4(a0, d0, a1, d1);
        ws.ab2[2 * lane + 1] = make_float4(a2, d2, a3, d3);
    }
    __syncwarp();

    const float4 b2v = b2s;
    const u64 bxy = pack2(b2v.x, b2v.y);
    const u64 bzw = pack2(b2v.z, b2v.w);

    // ---------------- Coarse pass: keys 2*lane, 2*lane+1 ----------------
    float kc0, kc1;
    float zca[2], dca[2];
    {
        float2 uc = reinterpret_cast<const float2*>(u_coarse + ray * NC)[lane];
        kc0 = (float)(2 * lane)     + uc.x;
        kc1 = (float)(2 * lane + 1) + uc.y;
        ws.kc[2 * lane]     = kc0;
        ws.kc[2 * lane + 1] = kc1;
        zca[0] = fmaf(kc0, zscale, nearv);
        zca[1] = fmaf(kc1, zscale, nearv);
        float znxt = __shfl_down_sync(0xffffffffu, zca[0], 1);
        if (lane == 31) znxt = farv;
        dca[0] = zca[1] - zca[0];
        dca[1] = znxt - zca[1];
    }
    float4 co[2];
    mlp2(ws.ab2, W2s, bxy, bzw, zca[0], zca[1], co[0], co[1]);

    float wgt[2];
    float4 coarse = composite<2>(co, zca, dca, wgt, lane);

    // ---------------- PDF / CDF over coarse weights ----------------
    {
        float p0 = wgt[0] + 1e-5f;
        float p1 = wgt[1] + 1e-5f;
        float tot = p0 + p1;
#pragma unroll
        for (int off = 16; off > 0; off >>= 1)
            tot += __shfl_xor_sync(0xffffffffu, tot, off);
        float inv = 1.0f / tot;
        float pdf0 = p0 * inv, pdf1 = p1 * inv;
        float sc = pdf0 + pdf1;
#pragma unroll
        for (int off = 1; off < 32; off <<= 1) {
            float v = __shfl_up_sync(0xffffffffu, sc, off);
            if (lane >= off) sc += v;
        }
        float excl = __shfl_up_sync(0xffffffffu, sc, 1);
        if (lane == 0) excl = 0.0f;
        float c1 = excl + pdf0;
        if (lane == 0) ws.u.cdf[0] = 0.0f;
        ws.u.cdf[2 * lane + 1] = c1;
        ws.u.cdf[2 * lane + 2] = c1 + pdf1;
    }
    __syncwarp();

    // ------------- Fine sampling: searchsorted(right) - 1, + jitter -------------
    float kf0, kf1;
    int bin0, bin1;
    {
        float2 uf = reinterpret_cast<const float2*>(u_fine   + ray * NC)[lane];
        float2 uj = reinterpret_cast<const float2*>(u_jitter + ray * NC)[lane];
        float us[2] = {uf.x, uf.y};
        float js[2] = {uj.x, uj.y};
        int   bn[2];
        float kv[2];
#pragma unroll
        for (int k = 0; k < 2; k++) {
            int lo = 0, hi = 65;   // count of cdf entries <= u
            while (lo < hi) {
                int mid = (lo + hi) >> 1;
                if (ws.u.cdf[mid] <= us[k]) lo = mid + 1; else hi = mid;
            }
            int ind = max(lo - 1, 0);     // may be 64
            bn[k] = ind;
            kv[k] = (float)ind + js[k];   // key in [0, 65)
        }
        kf0 = kv[0]; kf1 = kv[1]; bin0 = bn[0]; bin1 = bn[1];
        ws.kf[2 * lane]     = kf0;
        ws.kf[2 * lane + 1] = kf1;
    }
    __syncwarp();   // cdf dead from here; storage becomes zs/outs

    // ---------------- MLP on the 64 NEW fine samples only ----------------
    const float zn0 = fmaf(kf0, zscale, nearv);
    const float zn1 = fmaf(kf1, zscale, nearv);
    float4 fo[2];
    mlp2(ws.ab2, W2s, bxy, bzw, zn0, zn1, fo[0], fo[1]);

    // ---------------- Merge by rank (key space, coarse pre-sorted) ----------------
    {
        int posc0 = 2 * lane;          // coarse rank among coarse = own index
        int posc1 = 2 * lane + 1;
        int posf0 = 0, posf1 = 0;      // fine rank among fine (tie by index)
        const int if0 = 2 * lane, if1 = 2 * lane + 1;
        const float4* kf4 = reinterpret_cast<const float4*>(ws.kf);
#pragma unroll 4
        for (int q4 = 0; q4 < NC / 4; q4++) {
            float4 qv = kf4[q4];       // broadcast LDS.128, serves 4 keys
            const float qs[4] = {qv.x, qv.y, qv.z, qv.w};
#pragma unroll
            for (int c = 0; c < 4; c++) {
                const int j = 4 * q4 + c;
                const float q = qs[c];
                posc0 += (q < kc0);
                posc1 += (q < kc1);
                posf0 += (q < kf0) || (q == kf0 && j < if0);
                posf1 += (q < kf1) || (q == kf1 && j < if1);
            }
        }
        // coarse entries before each fine sample: bin + (kc[bin] <= kf)
        posf0 += (bin0 >= NC) ? NC : (bin0 + (ws.kc[bin0] <= kf0));
        posf1 += (bin1 >= NC) ? NC : (bin1 + (ws.kc[bin1] <= kf1));

        // scatter (z, MLP out) records into sorted order
        ws.u.m.zs[posc0] = zca[0];  ws.u.m.outs[posc0] = co[0];
        ws.u.m.zs[posc1] = zca[1];  ws.u.m.outs[posc1] = co[1];
        ws.u.m.zs[posf0] = zn0;     ws.u.m.outs[posf0] = fo[0];
        ws.u.m.zs[posf1] = zn1;     ws.u.m.outs[posf1] = fo[1];
    }
    __syncwarp();

    // ---------------- Fine composite: samples 4*lane .. 4*lane+3 ----------------
    float zf[4], df[4];
    float4 go[4];
    {
        float4 zq = *reinterpret_cast<const float4*>(&ws.u.m.zs[4 * lane]);
        zf[0] = zq.x; zf[1] = zq.y; zf[2] = zq.z; zf[3] = zq.w;
#pragma unroll
        for (int i = 0; i < 4; i++) go[i] = ws.u.m.outs[4 * lane + i];
        float znxt = __shfl_down_sync(0xffffffffu, zq.x, 1);
        if (lane == 31) znxt = farv;
        df[0] = zf[1] - zf[0];
        df[1] = zf[2] - zf[1];
        df[2] = zf[3] - zf[2];
        df[3] = znxt - zf[3];
    }
    float4 fine = composite<4>(go, zf, df, nullptr, lane);

    if (lane == 0) {
        float4* op = reinterpret_cast<float4*>(out + ray * 8);
        op[0] = make_float4(coarse.x, coarse.y, coarse.z, coarse.w);
        op[1] = make_float4(fine.x, fine.y, fine.z, fine.w);
    }
}

extern "C" void kernel_launch(void* const* d_in, const int* in_sizes, int n_in,
                              void* d_out, int out_size)
{
    const float* rays     = (const float*)d_in[0];
    const float* u_coarse = (const float*)d_in[1];
    const float* u_fine   = (const float*)d_in[2];
    const float* u_jitter = (const float*)d_in[3];
    const float* W1       = (const float*)d_in[4];
    const float* b1       = (const float*)d_in[5];
    const float* W2       = (const float*)d_in[6];
    const float* b2       = (const float*)d_in[7];
    float* out            = (float*)d_out;

    static bool carveout_set = false;
    if (!carveout_set) {
        cudaFuncSetAttribute(nerf_kernel,
                             cudaFuncAttributePreferredSharedMemoryCarveout,
                             cudaSharedmemCarveoutMaxShared);
        carveout_set = true;
    }

    const int R = in_sizes[0] / 8;          // 16384
    const int blocks = R / WPB;             // 4096
    nerf_kernel<<<blocks, WPB * 32>>>(rays, u_coarse, u_fine, u_jitter,
                                      W1, b1, W2, b2, out);
}

// round 6
// speedup vs baseline: 1.4750x; 1.4750x over previous
#include <cuda_runtime.h>

namespace {

constexpr int NC  = 64;    // coarse samples
constexpr int NA  = 128;   // total samples in fine pass
constexpr int HID = 128;
constexpr int WPB = 4;     // warps (rays) per block

using u64 = unsigned long long;

__device__ __forceinline__ u64 f32x2_fma(u64 a, u64 b, u64 c) {
    u64 d;
    asm("fma.rn.f32x2 %0, %1, %2, %3;" : "=l"(d) : "l"(a), "l"(b), "l"(c));
    return d;
}
__device__ __forceinline__ u64 pack2(float lo, float hi) {
    u64 d;
    asm("mov.b64 %0, {%1, %2};" : "=l"(d) : "f"(lo), "f"(hi));
    return d;
}
__device__ __forceinline__ float2 unpack2(u64 v) {
    float2 r;
    asm("mov.b64 {%0, %1}, %2;" : "=f"(r.x), "=f"(r.y) : "l"(v));
    return r;
}

struct alignas(16) WarpSh {
    float4 ab2[HID / 2];        // {a_j, a_j+1, b_j, b_j+1} per unit pair : 1024 B
    union {                     // lifetimes disjoint:
        float cdf[68];          //   cdf[0..64]  (pdf->sampling)
        struct {
            float  zs[NA];      //   sorted z            : 512 B
            float4 outs[NA];    //   sorted (r,g,b,sig)   : 2048 B
        } m;                    //   (merge->fine composite)
    } u;
    float kc[NC];               // coarse keys (sorted by construction)
    float kf[NC];               // fine keys
};                              // 4096 B

// MLP for 2 samples; f32x2 pair dimension = hidden-unit pairs.
// acc channels hold (even-unit sum, odd-unit sum); horizontal add at the end.
__device__ __forceinline__ void mlp2(
    const float4* __restrict__ ab2,   // {a_j, a_j+1, b_j, b_j+1}
    const float4* __restrict__ W2p,   // pair-transposed W2 (see setup)
    u64 bx0, u64 by0, u64 bz0, u64 bw0,   // (bias, 0)
    float z0, float z1, float4& o0, float4& o1)
{
    const u64 zz0 = pack2(z0, z0);
    const u64 zz1 = pack2(z1, z1);
    u64 a0x = bx0, a0y = by0, a0z = bz0, a0w = bw0;
    u64 a1x = bx0, a1y = by0, a1z = bz0, a1w = bw0;

#pragma unroll 8
    for (int j2 = 0; j2 < HID / 2; j2++) {
        float4 p  = ab2[j2];          // broadcast LDS.128
        float4 q0 = W2p[2 * j2];      // broadcast LDS.128
        float4 q1 = W2p[2 * j2 + 1];  // broadcast LDS.128
        u64 aa = pack2(p.x, p.y);     // adjacent halves of the load: free
        u64 bb = pack2(p.z, p.w);
        u64 wx = pack2(q0.x, q0.y);   // (w_jx, w_j+1,x)
        u64 wy = pack2(q0.z, q0.w);
        u64 wz = pack2(q1.x, q1.y);
        u64 ww = pack2(q1.z, q1.w);
        {   // sample 0
            float2 t = unpack2(f32x2_fma(zz0, bb, aa));
            u64 hh = pack2(fmaxf(t.x, 0.0f), fmaxf(t.y, 0.0f));
            a0x = f32x2_fma(hh, wx, a0x);
            a0y = f32x2_fma(hh, wy, a0y);
            a0z = f32x2_fma(hh, wz, a0z);
            a0w = f32x2_fma(hh, ww, a0w);
        }
        {   // sample 1
            float2 t = unpack2(f32x2_fma(zz1, bb, aa));
            u64 hh = pack2(fmaxf(t.x, 0.0f), fmaxf(t.y, 0.0f));
            a1x = f32x2_fma(hh, wx, a1x);
            a1y = f32x2_fma(hh, wy, a1y);
            a1z = f32x2_fma(hh, wz, a1z);
            a1w = f32x2_fma(hh, ww, a1w);
        }
    }
    float2 v;
    v = unpack2(a0x); o0.x = v.x + v.y;
    v = unpack2(a0y); o0.y = v.x + v.y;
    v = unpack2(a0z); o0.z = v.x + v.y;
    v = unpack2(a0w); o0.w = v.x + v.y;
    v = unpack2(a1x); o1.x = v.x + v.y;
    v = unpack2(a1y); o1.y = v.x + v.y;
    v = unpack2(a1z); o1.z = v.x + v.y;
    v = unpack2(a1w); o1.w = v.x + v.y;
}

// Alpha compositing over K depth-sorted samples/lane (lane-major order).
// o[i] = (r, g, b, sigma). Returns warp-summed (r, g, b, depth) on all lanes.
template <int K>
__device__ __forceinline__ float4 composite(
    const float4* o, const float* z, const float* delta, float* w_out, int lane)
{
    float alpha[K], f[K];
    float prod = 1.0f;
#pragma unroll
    for (int i = 0; i < K; i++) {
        float sig = fmaxf(o[i].w, 0.0f);
        alpha[i] = 1.0f - __expf(-delta[i] * sig);
        f[i] = 1.0f - alpha[i] + 1e-10f;
        prod *= f[i];
    }

    // exclusive warp prefix-product of per-lane transmittance factors
    float sc = prod;
#pragma unroll
    for (int off = 1; off < 32; off <<= 1) {
        float v = __shfl_up_sync(0xffffffffu, sc, off);
        if (lane >= off) sc *= v;
    }
    float T = __shfl_up_sync(0xffffffffu, sc, 1);
    if (lane == 0) T = 1.0f;

    float rx = 0.f, ry = 0.f, rz = 0.f, dd = 0.f;
#pragma unroll
    for (int i = 0; i < K; i++) {
        float w = alpha[i] * T;
        if (w_out) w_out[i] = w;
        rx = fmaf(w, o[i].x, rx);
        ry = fmaf(w, o[i].y, ry);
        rz = fmaf(w, o[i].z, rz);
        dd = fmaf(w, z[i],   dd);
        T *= f[i];
    }
#pragma unroll
    for (int off = 16; off > 0; off >>= 1) {
        rx += __shfl_xor_sync(0xffffffffu, rx, off);
        ry += __shfl_xor_sync(0xffffffffu, ry, off);
        rz += __shfl_xor_sync(0xffffffffu, rz, off);
        dd += __shfl_xor_sync(0xffffffffu, dd, off);
    }
    return make_float4(rx, ry, rz, dd);
}

} // namespace

__global__ void __launch_bounds__(WPB * 32)
nerf_kernel(const float* __restrict__ rays,
            const float* __restrict__ u_coarse,
            const float* __restrict__ u_fine,
            const float* __restrict__ u_jitter,
            const float* __restrict__ W1,   // (3, 128)
            const float* __restrict__ b1,   // (128,)
            const float* __restrict__ W2,   // (128, 4)
            const float* __restrict__ b2,   // (4,)
            float* __restrict__ out)        // (R, 8)
{
    __shared__ float4 W2p[HID];     // pair-transposed layer-2 weights
    __shared__ float4 b2s;
    __shared__ WarpSh wsall[WPB];

    const int tid  = threadIdx.x;
    const int wid  = tid >> 5;
    const int lane = tid & 31;
    const int ray  = blockIdx.x * WPB + wid;

    if (tid < HID / 2) {
        float4 w0 = reinterpret_cast<const float4*>(W2)[2 * tid];
        float4 w1 = reinterpret_cast<const float4*>(W2)[2 * tid + 1];
        W2p[2 * tid]     = make_float4(w0.x, w1.x, w0.y, w1.y);
        W2p[2 * tid + 1] = make_float4(w0.z, w1.z, w0.w, w1.w);
    }
    if (tid == HID / 2) b2s = *reinterpret_cast<const float4*>(b2);
    __syncthreads();

    WarpSh& ws = wsall[wid];
    const float* rp = rays + ray * 8;   // broadcast loads
    const float ox = rp[0], oy = rp[1], oz = rp[2];
    const float dx = rp[3], dy = rp[4], dz = rp[5];
    const float nearv = rp[6], farv = rp[7];
    const float zscale = (farv - nearv) * (1.0f / NC);   // z = near + key*zscale

    // Per-ray layer-1 affine: lane handles units 4*lane .. 4*lane+3 (float4 rows)
    {
        float4 w0 = reinterpret_cast<const float4*>(W1)[lane];             // row 0
        float4 w1 = reinterpret_cast<const float4*>(W1 + HID)[lane];       // row 1
        float4 w2 = reinterpret_cast<const float4*>(W1 + 2 * HID)[lane];   // row 2
        float4 bb = reinterpret_cast<const float4*>(b1)[lane];
        float a0 = fmaf(ox, w0.x, fmaf(oy, w1.x, fmaf(oz, w2.x, bb.x)));
        float a1 = fmaf(ox, w0.y, fmaf(oy, w1.y, fmaf(oz, w2.y, bb.y)));
        float a2 = fmaf(ox, w0.z, fmaf(oy, w1.z, fmaf(oz, w2.z, bb.z)));
        float a3 = fmaf(ox, w0.w, fmaf(oy, w1.w, fmaf(oz, w2.w, bb.w)));
        float d0 = fmaf(dx, w0.x, fmaf(dy, w1.x, dz * w2.x));
        float d1 = fmaf(dx, w0.y, fmaf(dy, w1.y, dz * w2.y));
        float d2 = fmaf(dx, w0.z, fmaf(dy, w1.z, dz * w2.z));
        float d3 = fmaf(dx, w0.w, fmaf(dy, w1.w, dz * w2.w));
        ws.ab2[2 * lane]     = make_float4(a0, a1, d0, d1);
        ws.ab2[2 * lane + 1] = make_float4(a2, a3, d2, d3);
    }
    __syncwarp();

    const float4 b2v = b2s;
    const u64 bx0 = pack2(b2v.x, 0.0f);
    const u64 by0 = pack2(b2v.y, 0.0f);
    const u64 bz0 = pack2(b2v.z, 0.0f);
    const u64 bw0 = pack2(b2v.w, 0.0f);

    // ---------------- Coarse pass: keys 2*lane, 2*lane+1 ----------------
    float kc0, kc1;
    float zca[2], dca[2];
    {
        float2 uc = reinterpret_cast<const float2*>(u_coarse + ray * NC)[lane];
        kc0 = (float)(2 * lane)     + uc.x;
        kc1 = (float)(2 * lane + 1) + uc.y;
        ws.kc[2 * lane]     = kc0;
        ws.kc[2 * lane + 1] = kc1;
        zca[0] = fmaf(kc0, zscale, nearv);
        zca[1] = fmaf(kc1, zscale, nearv);
        float znxt = __shfl_down_sync(0xffffffffu, zca[0], 1);
        if (lane == 31) znxt = farv;
        dca[0] = zca[1] - zca[0];
        dca[1] = znxt - zca[1];
    }
    float4 co[2];
    mlp2(ws.ab2, W2p, bx0, by0, bz0, bw0, zca[0], zca[1], co[0], co[1]);

    float wgt[2];
    float4 coarse = composite<2>(co, zca, dca, wgt, lane);

    // ---------------- PDF / CDF over coarse weights ----------------
    {
        float p0 = wgt[0] + 1e-5f;
        float p1 = wgt[1] + 1e-5f;
        float tot = p0 + p1;
#pragma unroll
        for (int off = 16; off > 0; off >>= 1)
            tot += __shfl_xor_sync(0xffffffffu, tot, off);
        float inv = 1.0f / tot;
        float pdf0 = p0 * inv, pdf1 = p1 * inv;
        float sc = pdf0 + pdf1;
#pragma unroll
        for (int off = 1; off < 32; off <<= 1) {
            float v = __shfl_up_sync(0xffffffffu, sc, off);
            if (lane >= off) sc += v;
        }
        float excl = __shfl_up_sync(0xffffffffu, sc, 1);
        if (lane == 0) excl = 0.0f;
        float c1 = excl + pdf0;
        if (lane == 0) ws.u.cdf[0] = 0.0f;
        ws.u.cdf[2 * lane + 1] = c1;
        ws.u.cdf[2 * lane + 2] = c1 + pdf1;
    }
    __syncwarp();

    // ------------- Fine sampling: searchsorted(right) - 1, + jitter -------------
    float kf0, kf1;
    int bin0, bin1;
    {
        float2 uf = reinterpret_cast<const float2*>(u_fine   + ray * NC)[lane];
        float2 uj = reinterpret_cast<const float2*>(u_jitter + ray * NC)[lane];
        float us[2] = {uf.x, uf.y};
        float js[2] = {uj.x, uj.y};
        int   bn[2];
        float kv[2];
#pragma unroll
        for (int k = 0; k < 2; k++) {
            int lo = 0, hi = 65;   // count of cdf entries <= u
            while (lo < hi) {
                int mid = (lo + hi) >> 1;
                if (ws.u.cdf[mid] <= us[k]) lo = mid + 1; else hi = mid;
            }
            int ind = max(lo - 1, 0);     // may be 64
            bn[k] = ind;
            kv[k] = (float)ind + js[k];   // key in [0, 65)
        }
        kf0 = kv[0]; kf1 = kv[1]; bin0 = bn[0]; bin1 = bn[1];
        ws.kf[2 * lane]     = kf0;
        ws.kf[2 * lane + 1] = kf1;
    }
    __syncwarp();   // cdf dead from here; storage becomes zs/outs

    // ---------------- MLP on the 64 NEW fine samples only ----------------
    const float zn0 = fmaf(kf0, zscale, nearv);
    const float zn1 = fmaf(kf1, zscale, nearv);
    float4 fo[2];
    mlp2(ws.ab2, W2p, bx0, by0, bz0, bw0, zn0, zn1, fo[0], fo[1]);

    // ---------------- Merge by rank (key space, coarse pre-sorted) ----------------
    {
        int posc0 = 2 * lane;          // coarse rank among coarse = own index
        int posc1 = 2 * lane + 1;
        int posf0 = 0, posf1 = 0;      // fine rank among fine (tie by index)
        const int if0 = 2 * lane, if1 = 2 * lane + 1;
        const float4* kf4 = reinterpret_cast<const float4*>(ws.kf);
#pragma unroll 4
        for (int q4 = 0; q4 < NC / 4; q4++) {
            float4 qv = kf4[q4];       // broadcast LDS.128, serves 4 keys
            const float qs[4] = {qv.x, qv.y, qv.z, qv.w};
#pragma unroll
            for (int c = 0; c < 4; c++) {
                const int j = 4 * q4 + c;
                const float q = qs[c];
                posc0 += (q < kc0);
                posc1 += (q < kc1);
                posf0 += (q < kf0) || (q == kf0 && j < if0);
                posf1 += (q < kf1) || (q == kf1 && j < if1);
            }
        }
        // coarse entries before each fine sample: bin + (kc[bin] <= kf)
        posf0 += (bin0 >= NC) ? NC : (bin0 + (ws.kc[bin0] <= kf0));
        posf1 += (bin1 >= NC) ? NC : (bin1 + (ws.kc[bin1] <= kf1));

        // scatter (z, MLP out) records into sorted order
        ws.u.m.zs[posc0] = zca[0];  ws.u.m.outs[posc0] = co[0];
        ws.u.m.zs[posc1] = zca[1];  ws.u.m.outs[posc1] = co[1];
        ws.u.m.zs[posf0] = zn0;     ws.u.m.outs[posf0] = fo[0];
        ws.u.m.zs[posf1] = zn1;     ws.u.m.outs[posf1] = fo[1];
    }
    __syncwarp();

    // ---------------- Fine composite: samples 4*lane .. 4*lane+3 ----------------
    float zf[4], df[4];
    float4 go[4];
    {
        float4 zq = *reinterpret_cast<const float4*>(&ws.u.m.zs[4 * lane]);
        zf[0] = zq.x; zf[1] = zq.y; zf[2] = zq.z; zf[3] = zq.w;
#pragma unroll
        for (int i = 0; i < 4; i++) go[i] = ws.u.m.outs[4 * lane + i];
        float znxt = __shfl_down_sync(0xffffffffu, zq.x, 1);
        if (lane == 31) znxt = farv;
        df[0] = zf[1] - zf[0];
        df[1] = zf[2] - zf[1];
        df[2] = zf[3] - zf[2];
        df[3] = znxt - zf[3];
    }
    float4 fine = composite<4>(go, zf, df, nullptr, lane);

    if (lane == 0) {
        float4* op = reinterpret_cast<float4*>(out + ray * 8);
        op[0] = make_float4(coarse.x, coarse.y, coarse.z, coarse.w);
        op[1] = make_float4(fine.x, fine.y, fine.z, fine.w);
    }
}

extern "C" void kernel_launch(void* const* d_in, const int* in_sizes, int n_in,
                              void* d_out, int out_size)
{
    const float* rays     = (const float*)d_in[0];
    const float* u_coarse = (const float*)d_in[1];
    const float* u_fine   = (const float*)d_in[2];
    const float* u_jitter = (const float*)d_in[3];
    const float* W1       = (const float*)d_in[4];
    const float* b1       = (const float*)d_in[5];
    const float* W2       = (const float*)d_in[6];
    const float* b2       = (const float*)d_in[7];
    float* out            = (float*)d_out;

    static bool carveout_set = false;
    if (!carveout_set) {
        cudaFuncSetAttribute(nerf_kernel,
                             cudaFuncAttributePreferredSharedMemoryCarveout,
                             cudaSharedmemCarveoutMaxShared);
        carveout_set = true;
    }

    const int R = in_sizes[0] / 8;          // 16384
    const int blocks = R / WPB;             // 4096
    nerf_kernel<<<blocks, WPB * 32>>>(rays, u_coarse, u_fine, u_jitter,
                                      W1, b1, W2, b2, out);
}